// round 10
// baseline (speedup 1.0000x reference)
#include <cuda_runtime.h>
#include <cstdint>

#define Bz 32
#define Hh 512
#define Ll 2
#define Tt 20
#define Vv 10000
#define Ss 49
#define GRID 148

typedef unsigned long long ull;

// ---------------- device state (no allocations allowed) ----------------
__device__ __align__(16) float g_embT[Hh * Bz];          // k4b4 layout
__device__ __align__(16) float g_hA[Ll][Hh * Bz];        // gated h (LSTM input), k4b4
__device__ __align__(16) float g_hB[Ll][Hh * Bz];        // post-LSTM h, k4b4
__device__ __align__(16) float g_cT[Ll][Hh * Bz];        // plain [k*32+b]
__device__ __align__(16) float g_attnT[Ll][Hh * Bz];     // k4b4
__device__ float g_q[Ll][Hh][Bz];
__device__ float g_keysT[Bz * Ss * Hh];                  // [b][s][d]
__device__ float g_vals[Bz * Hh * Ss];                   // [b][d][s]
__device__ ull   g_amax[Bz];
__device__ int   g_count;
__device__ int   g_gen;

// ---------------- helpers ----------------
__device__ __forceinline__ void fma2(ull& d, ull a, ull b) {
    asm("fma.rn.f32x2 %0, %1, %2, %0;" : "+l"(d) : "l"(a), "l"(b));
}
__device__ __forceinline__ float unpk_sum(ull v) {
    float lo, hi;
    asm("mov.b64 {%0,%1}, %2;" : "=f"(lo), "=f"(hi) : "l"(v));
    return lo + hi;
}
__device__ __forceinline__ int K4B(int k, int b) { return ((k >> 2) * Bz + b) * 4 + (k & 3); }
__device__ __forceinline__ float sigf(float x) { return 1.0f / (1.0f + expf(-x)); }
__device__ __forceinline__ unsigned fkey(float f) {
    unsigned u = __float_as_uint(f);
    return (u & 0x80000000u) ? ~u : (u | 0x80000000u);
}

// grid-wide barrier, re-entrant across launches via base-relative generations.
__device__ __forceinline__ void gridbar(int gen) {
    __syncthreads();
    if (threadIdx.x == 0) {
        __threadfence();
        if (atomicAdd(&g_count, 1) == GRID - 1) {
            g_count = 0;
            __threadfence();
            asm volatile("st.release.gpu.b32 [%0], %1;" :: "l"(&g_gen), "r"(gen) : "memory");
        } else {
            int v;
            do {
                asm volatile("ld.acquire.gpu.b32 %0, [%1];" : "=r"(v) : "l"(&g_gen) : "memory");
            } while (v < gen);
        }
    }
    __syncthreads();
}

// ---------------- keys/values precompute (separate kernel, once per launch) ----------------
__global__ void k_kv(const float* __restrict__ img, const float* __restrict__ Wk,
                     const float* __restrict__ bk, const float* __restrict__ Wv,
                     const float* __restrict__ bv) {
    int bd = blockIdx.x;               // b*512 + d
    int b = bd >> 9, d = bd & 511;
    __shared__ float ch[Ss];
    int tid = threadIdx.x;
    if (tid < Ss) ch[tid] = img[(b * Hh + d) * Ss + tid];
    __syncthreads();
    if (tid < Ss) {
        int s = tid;
        float ka = bk[s], va = bv[s];
        const float* wkr = Wk + s * Ss;
        const float* wvr = Wv + s * Ss;
#pragma unroll
        for (int s2 = 0; s2 < Ss; s2++) {
            float c = ch[s2];
            ka = fmaf(c, wkr[s2], ka);
            va = fmaf(c, wvr[s2], va);
        }
        g_keysT[(b * Ss + s) * Hh + d] = tanhf(ka);
        g_vals[(b * Hh + d) * Ss + s] = tanhf(va);
    }
}

// ================= persistent-kernel phases =================

// LSTM layer: blocks 0..127, 4 gate-rows per block, split-K=4 (16 warps).
// Weights live in SMEM (persistently cached); activations come via L1.
// smWl layout: (rl*4+g)*1024 + [0..511]=Wih row, [512..1023]=Whh row.
__device__ __forceinline__ void phase_lstm(
    float* red, const float* smWl, const float* xsrc, int layer,
    const float* __restrict__ bih, const float* __restrict__ bhh) {
    int blk = blockIdx.x;
    if (blk >= 128) return;
    int tid = threadIdx.x;
    int wid = tid >> 5, b = tid & 31;
    int rl = wid >> 2, split = wid & 3;
    int jj = blk * 4 + rl;
    const longlong2* xT = (const longlong2*)xsrc;
    const longlong2* hT = (const longlong2*)g_hA[layer];

    ull acc[4] = {0ull, 0ull, 0ull, 0ull};
    int k4b = split * 32;
#pragma unroll 2
    for (int i = 0; i < 32; i++) {
        int k4 = k4b + i;
        longlong2 xv = xT[k4 * Bz + b];
        longlong2 hv = hT[k4 * Bz + b];
#pragma unroll
        for (int g = 0; g < 4; g++) {
            const float* wrow = smWl + (rl * 4 + g) * 1024;
            longlong2 wi = *(const longlong2*)(wrow + k4 * 4);
            longlong2 wh = *(const longlong2*)(wrow + 512 + k4 * 4);
            fma2(acc[g], (ull)wi.x, (ull)xv.x);
            fma2(acc[g], (ull)wi.y, (ull)xv.y);
            fma2(acc[g], (ull)wh.x, (ull)hv.x);
            fma2(acc[g], (ull)wh.y, (ull)hv.y);
        }
    }
#pragma unroll
    for (int g = 0; g < 4; g++)
        red[((rl * 4 + split) * 4 + g) * 32 + b] = unpk_sum(acc[g]);
    __syncthreads();
    if (tid < 128) {
        int r2 = tid >> 5, bb = tid & 31;
        int j2 = blk * 4 + r2;
        float gate[4];
#pragma unroll
        for (int g = 0; g < 4; g++) {
            float s = 0.f;
#pragma unroll
            for (int sp = 0; sp < 4; sp++) s += red[((r2 * 4 + sp) * 4 + g) * 32 + bb];
            gate[g] = s + bih[g * Hh + j2] + bhh[g * Hh + j2];
        }
        float iv = sigf(gate[0]), fv = sigf(gate[1]);
        float gv = tanhf(gate[2]), ov = sigf(gate[3]);
        int ci = j2 * Bz + bb;
        float c2 = fv * g_cT[layer][ci] + iv * gv;
        g_cT[layer][ci] = c2;
        g_hB[layer][K4B(j2, bb)] = ov * tanhf(c2);
    }
}

// projection (+ fused q). Interleaved tasks: task = wid*148 + blk.
// tasks 0..1249: 8 vocab rows each (exactly 10000). tasks 1250..1761: one q dim (both layers).
// Activations read directly through L1 (hot: 64KB arrays broadcast to all blocks).
__device__ __forceinline__ void phase_proj(
    ull* samax, const longlong2* __restrict__ W, const float* __restrict__ pb,
    float* __restrict__ res, int t, int src_emb, int do_amax,
    int doq, const longlong2* __restrict__ Wq, const float* __restrict__ bq) {
    int tid = threadIdx.x;
    if (do_amax) {
        if (tid < Bz) samax[tid] = 0ull;
        __syncthreads();
    }
    int task = (tid >> 5) * GRID + blockIdx.x;
    int b = tid & 31;
    const longlong2* xT = src_emb ? (const longlong2*)g_embT : (const longlong2*)g_hB[1];
    if (task < 1250) {
        int v0 = task * 8;
        ull acc[8] = {0ull, 0ull, 0ull, 0ull, 0ull, 0ull, 0ull, 0ull};
#pragma unroll 2
        for (int k4 = 0; k4 < Hh / 4; k4++) {
            longlong2 xv = xT[k4 * Bz + b];
#pragma unroll
            for (int r = 0; r < 8; r++) {
                longlong2 wv = W[(v0 + r) * (Hh / 4) + k4];
                fma2(acc[r], (ull)wv.x, (ull)xv.x);
                fma2(acc[r], (ull)wv.y, (ull)xv.y);
            }
        }
        ull best = 0ull;
#pragma unroll
        for (int r = 0; r < 8; r++) {
            int v = v0 + r;
            float lg = unpk_sum(acc[r]) + pb[v];
            res[b * (Vv * Tt) + v * Tt + t] = lg;
            ull pk = ((ull)fkey(lg) << 32) | (unsigned)(~(unsigned)v);
            if (pk > best) best = pk;
        }
        if (do_amax) atomicMax(&samax[b], best);
    } else if (doq && task < 1250 + Hh) {
        int d = task - 1250;
        const longlong2* h0 = (const longlong2*)g_hB[0];
        const longlong2* h1 = (const longlong2*)g_hB[1];
        ull a0 = 0ull, a1 = 0ull;
#pragma unroll 2
        for (int k4 = 0; k4 < Hh / 4; k4++) {
            longlong2 wv = Wq[d * (Hh / 4) + k4];
            longlong2 x0 = h0[k4 * Bz + b];
            longlong2 x1 = h1[k4 * Bz + b];
            fma2(a0, (ull)wv.x, (ull)x0.x);
            fma2(a0, (ull)wv.y, (ull)x0.y);
            fma2(a1, (ull)wv.x, (ull)x1.x);
            fma2(a1, (ull)wv.y, (ull)x1.y);
        }
        float bv = bq[d];
        g_q[0][d][b] = tanhf(unpk_sum(a0) + bv);
        g_q[1][d][b] = tanhf(unpk_sum(a1) + bv);
    }
    if (do_amax) { __syncthreads(); if (tid < Bz) atomicMax(&g_amax[tid], samax[tid]); }
}

// attention: blocks 0..63 = (l,b); l==0 blocks also gather next-token embedding.
__device__ __forceinline__ void phase_att(float* sq, float* sw, const float* __restrict__ embed) {
    int blk = blockIdx.x;
    if (blk >= 64) return;
    int l = blk >> 5, b = blk & 31;
    int tid = threadIdx.x;
    for (int d = tid; d < Hh; d += 512) sq[d] = g_q[l][d][b];
    __syncthreads();
    int w = tid >> 5, lane = tid & 31;
    for (int s = w; s < Ss; s += 16) {
        const float* kr = g_keysT + (b * Ss + s) * Hh;
        float acc = 0.f;
        for (int d = lane; d < Hh; d += 32) acc = fmaf(sq[d], kr[d], acc);
#pragma unroll
        for (int o = 16; o > 0; o >>= 1) acc += __shfl_down_sync(0xffffffffu, acc, o);
        if (lane == 0) sw[s] = acc * (1.0f / 7.0f);
    }
    __syncthreads();
    if (w == 0) {
        float v0 = (lane < Ss) ? sw[lane] : -3.4e38f;
        float v1 = (lane + 32 < Ss) ? sw[lane + 32] : -3.4e38f;
        float m = fmaxf(v0, v1);
#pragma unroll
        for (int o = 16; o > 0; o >>= 1) m = fmaxf(m, __shfl_xor_sync(0xffffffffu, m, o));
        float e0 = (lane < Ss) ? expf(v0 - m) : 0.f;
        float e1 = (lane + 32 < Ss) ? expf(v1 - m) : 0.f;
        float sum = e0 + e1;
#pragma unroll
        for (int o = 16; o > 0; o >>= 1) sum += __shfl_xor_sync(0xffffffffu, sum, o);
        float inv = 1.0f / sum;
        if (lane < Ss) sw[lane] = e0 * inv;
        if (lane + 32 < Ss) sw[lane + 32] = e1 * inv;
    }
    __syncthreads();
    for (int d = tid; d < Hh; d += 512) {
        const float* vr = g_vals + (b * Hh + d) * Ss;
        float a = 0.f;
#pragma unroll
        for (int s = 0; s < Ss; s++) a = fmaf(sw[s], vr[s], a);
        g_attnT[l][K4B(d, b)] = a;
    }
    if (l == 0) {
        unsigned vtok = ~(unsigned)(g_amax[b]);
        for (int k = tid; k < Hh; k += 512)
            g_embT[K4B(k, b)] = embed[(size_t)vtok * Hh + k];
        __syncthreads();
        if (tid == 0) g_amax[b] = 0ull;
    }
}

// gated hidden update: blocks 0..127, 4 output dims per block, split-K=16.
__device__ __forceinline__ void phase_hatt(float* red, const longlong2* __restrict__ Wh,
                                           const float* __restrict__ hb) {
    int blk = blockIdx.x;
    if (blk >= 128) return;
    int tid = threadIdx.x;
    int wid = tid >> 5, b = tid & 31;
    int d0 = blk * 4;
    const longlong2* at0 = (const longlong2*)g_attnT[0];
    const longlong2* at1 = (const longlong2*)g_attnT[1];
    const longlong2* h0 = (const longlong2*)g_hB[0];
    const longlong2* h1 = (const longlong2*)g_hB[1];
    ull a0[4] = {0ull, 0ull, 0ull, 0ull}, a1[4] = {0ull, 0ull, 0ull, 0ull};
    int k4b = wid * 8;
#pragma unroll
    for (int i = 0; i < 8; i++) {
        int k4 = k4b + i;
        longlong2 av0 = at0[k4 * Bz + b], av1 = at1[k4 * Bz + b];
        longlong2 hv0 = h0[k4 * Bz + b], hv1 = h1[k4 * Bz + b];
#pragma unroll
        for (int r = 0; r < 4; r++) {
            int row = d0 + r;
            longlong2 wA = Wh[row * 256 + k4];
            longlong2 wH = Wh[row * 256 + 128 + k4];
            fma2(a0[r], (ull)wA.x, (ull)av0.x);
            fma2(a0[r], (ull)wA.y, (ull)av0.y);
            fma2(a0[r], (ull)wH.x, (ull)hv0.x);
            fma2(a0[r], (ull)wH.y, (ull)hv0.y);
            fma2(a1[r], (ull)wA.x, (ull)av1.x);
            fma2(a1[r], (ull)wA.y, (ull)av1.y);
            fma2(a1[r], (ull)wH.x, (ull)hv1.x);
            fma2(a1[r], (ull)wH.y, (ull)hv1.y);
        }
    }
#pragma unroll
    for (int r = 0; r < 4; r++) {
        red[(wid * 8 + r) * 32 + b] = unpk_sum(a0[r]);
        red[(wid * 8 + r + 4) * 32 + b] = unpk_sum(a1[r]);
    }
    __syncthreads();
    if (tid < 128) {
        int r = tid >> 5, bb = tid & 31;
        int d = d0 + r;
        float s0 = 0.f, s1 = 0.f;
#pragma unroll
        for (int sp = 0; sp < 16; sp++) {
            s0 += red[(sp * 8 + r) * 32 + bb];
            s1 += red[(sp * 8 + r + 4) * 32 + bb];
        }
        float bv = hb[d];
        g_hA[0][K4B(d, bb)] = tanhf(s0 + bv);
        g_hA[1][K4B(d, bb)] = tanhf(s1 + bv);
    }
}

// ---------------- the persistent time-loop kernel (init folded in) ----------------
__global__ __launch_bounds__(512, 1) void k_loop(
    const float* __restrict__ pooled, const float* __restrict__ embed,
    const int* __restrict__ sosp,
    const float* __restrict__ Wih, const float* __restrict__ Whh,
    const float* __restrict__ bih, const float* __restrict__ bhh,
    const longlong2* __restrict__ projW, const float* __restrict__ projb,
    const longlong2* __restrict__ Wq, const float* __restrict__ bq,
    const longlong2* __restrict__ hattW, const float* __restrict__ hattb,
    float* __restrict__ res) {
    extern __shared__ float smW[];         // 128KB: persistent LSTM weight cache
    __shared__ float red[16 * 8 * 32];     // 16KB (lstm uses first 8KB)
    __shared__ float sq[Hh];
    __shared__ float sw[64];
    __shared__ ull samax[Bz];
    __shared__ int s_base;

    // base generation (re-entrant barrier across launches)
    if (threadIdx.x == 0) s_base = *(volatile int*)&g_gen;
    __syncthreads();
    int gen = s_base;

    // ---- init phase: global state + persistent LSTM weight cache ----
    {
        int i = blockIdx.x * 512 + threadIdx.x;
        int sos = sosp[0];
        if (i < Ll * Hh * Bz) {
            int l = i / (Hh * Bz);
            int r = i % (Hh * Bz);
            int k = r >> 5, b = r & 31;
            float pv = pooled[b * Hh + k];
            g_hA[l][K4B(k, b)] = pv;
            g_cT[l][k * Bz + b] = pv;
        }
        if (i < Hh * Bz) {
            int k = i >> 5, b = i & 31;
            g_embT[K4B(k, b)] = embed[sos * Hh + k];
        }
        if (i < Bz) g_amax[i] = 0ull;

        // weight cache: smW[l*16384 + (rl*4+g)*1024 + half*512 + k]
        if (blockIdx.x < 128) {
            float4* dst = (float4*)smW;
            for (int q4 = threadIdx.x; q4 < 8192; q4 += 512) {
                int lin = q4 * 4;
                int l = lin >> 14;
                int rem = lin & 16383;
                int rg = rem >> 10;            // (rl*4+g)
                int within = rem & 1023;
                int half = within >> 9;
                int k = within & 511;
                int rl = rg >> 2, g = rg & 3;
                int row = g * Hh + blockIdx.x * 4 + rl;
                const float* src = (half == 0 ? Wih : Whh) + (size_t)l * 4 * Hh * Hh + row * Hh + k;
                dst[q4] = *(const float4*)src;
            }
        }
        __syncthreads();
    }
    gridbar(++gen);

    // t = 0 column from the <SOS> embedding (no argmax, no q)
    phase_proj(samax, projW, projb, res, 0, 1, 0, 0, Wq, bq);
    gridbar(++gen);

    for (int t = 1; t < Tt; t++) {
        phase_lstm(red, smW, g_embT, 0, bih, bhh);
        gridbar(++gen);
        phase_lstm(red, smW + 16384, g_hB[0], 1, bih + 4 * Hh, bhh + 4 * Hh);
        gridbar(++gen);
        phase_proj(samax, projW, projb, res, t, 0, 1, 1, Wq, bq);
        gridbar(++gen);
        phase_att(sq, sw, embed);
        gridbar(++gen);
        phase_hatt(red, hattW, hattb);
        gridbar(++gen);
    }
}

// ---------------- launch ----------------
extern "C" void kernel_launch(void* const* d_in, const int* in_sizes, int n_in,
                              void* d_out, int out_size) {
    (void)in_sizes; (void)n_in; (void)out_size;
    const float* img    = (const float*)d_in[0];
    const float* pooled = (const float*)d_in[1];
    const float* embed  = (const float*)d_in[2];
    const float* Wq     = (const float*)d_in[3];
    const float* bq     = (const float*)d_in[4];
    const float* Wk     = (const float*)d_in[5];
    const float* bk     = (const float*)d_in[6];
    const float* Wv     = (const float*)d_in[7];
    const float* bv     = (const float*)d_in[8];
    const float* Wih    = (const float*)d_in[9];
    const float* Whh    = (const float*)d_in[10];
    const float* bih    = (const float*)d_in[11];
    const float* bhh    = (const float*)d_in[12];
    const float* projW  = (const float*)d_in[13];
    const float* projb  = (const float*)d_in[14];
    const float* hattW  = (const float*)d_in[15];
    const float* hattb  = (const float*)d_in[16];
    const int*   sosp   = (const int*)d_in[17];
    float* res = (float*)d_out;

    cudaFuncSetAttribute(k_loop, cudaFuncAttributeMaxDynamicSharedMemorySize, 131072);
    k_kv<<<Bz * Hh, 64>>>(img, Wk, bk, Wv, bv);
    k_loop<<<GRID, 512, 131072>>>(pooled, embed, sosp,
                                  Wih, Whh, bih, bhh,
                                  (const longlong2*)projW, projb,
                                  (const longlong2*)Wq, bq,
                                  (const longlong2*)hattW, hattb,
                                  res);
}

// round 11
// speedup vs baseline: 1.5148x; 1.5148x over previous
#include <cuda_runtime.h>
#include <cstdint>

#define Bz 32
#define Hh 512
#define Ll 2
#define Tt 20
#define Vv 10000
#define Ss 49
#define GRID 148

typedef unsigned long long ull;

// ---------------- device state (no allocations allowed) ----------------
__device__ __align__(16) float g_embT[Hh * Bz];          // k4b4 layout
__device__ __align__(16) float g_hA[Ll][Hh * Bz];        // gated h (LSTM input), k4b4
__device__ __align__(16) float g_hB[Ll][Hh * Bz];        // post-LSTM h, k4b4
__device__ __align__(16) float g_cT[Ll][Hh * Bz];        // plain [k*32+b]
__device__ __align__(16) float g_attnT[Ll][Hh * Bz];     // k4b4
__device__ float g_q[Ll][Hh][Bz];
__device__ float g_keysT[Bz * Ss * Hh];                  // [b][s][d]
__device__ float g_vals[Bz * Hh * Ss];                   // [b][d][s]
__device__ ull   g_amax[Bz];
__device__ int   g_count,  g_gen;    // full-grid barrier
__device__ int   gA_count, gA_gen;   // group A (blocks 64..147, n=84)
__device__ int   gB_count, gB_gen;   // group B (blocks 0..63,  n=64)

// ---------------- helpers ----------------
__device__ __forceinline__ void fma2(ull& d, ull a, ull b) {
    asm("fma.rn.f32x2 %0, %1, %2, %0;" : "+l"(d) : "l"(a), "l"(b));
}
__device__ __forceinline__ float unpk_sum(ull v) {
    float lo, hi;
    asm("mov.b64 {%0,%1}, %2;" : "=f"(lo), "=f"(hi) : "l"(v));
    return lo + hi;
}
__device__ __forceinline__ longlong2 ldg_cs(const longlong2* p) {
    longlong2 v;
    asm("ld.global.cs.v2.u64 {%0,%1}, [%2];" : "=l"(v.x), "=l"(v.y) : "l"(p));
    return v;
}
__device__ __forceinline__ void stg_cs(float* p, float v) {
    asm("st.global.cs.f32 [%0], %1;" :: "l"(p), "f"(v) : "memory");
}
__device__ __forceinline__ int K4B(int k, int b) { return ((k >> 2) * Bz + b) * 4 + (k & 3); }
__device__ __forceinline__ float sigf(float x) { return 1.0f / (1.0f + expf(-x)); }
__device__ __forceinline__ unsigned fkey(float f) {
    unsigned u = __float_as_uint(f);
    return (u & 0x80000000u) ? ~u : (u | 0x80000000u);
}

// barrier over n blocks (monotonic generation; co-residency guaranteed at grid=148)
__device__ __forceinline__ void bar_n(int* cnt, int* genp, int n, int gen) {
    __syncthreads();
    if (threadIdx.x == 0) {
        __threadfence();
        if (atomicAdd(cnt, 1) == n - 1) {
            *cnt = 0;
            __threadfence();
            asm volatile("st.release.gpu.b32 [%0], %1;" :: "l"(genp), "r"(gen) : "memory");
        } else {
            int v;
            do {
                asm volatile("ld.acquire.gpu.b32 %0, [%1];" : "=r"(v) : "l"(genp) : "memory");
            } while (v < gen);
        }
    }
    __syncthreads();
}

// ---------------- keys/values precompute (separate kernel, once per launch) ----------------
__global__ void k_kv(const float* __restrict__ img, const float* __restrict__ Wk,
                     const float* __restrict__ bk, const float* __restrict__ Wv,
                     const float* __restrict__ bv) {
    int bd = blockIdx.x;               // b*512 + d
    int b = bd >> 9, d = bd & 511;
    __shared__ float ch[Ss];
    int tid = threadIdx.x;
    if (tid < Ss) ch[tid] = img[(b * Hh + d) * Ss + tid];
    __syncthreads();
    if (tid < Ss) {
        int s = tid;
        float ka = bk[s], va = bv[s];
        const float* wkr = Wk + s * Ss;
        const float* wvr = Wv + s * Ss;
#pragma unroll
        for (int s2 = 0; s2 < Ss; s2++) {
            float c = ch[s2];
            ka = fmaf(c, wkr[s2], ka);
            va = fmaf(c, wvr[s2], va);
        }
        g_keysT[(b * Ss + s) * Hh + d] = tanhf(ka);
        g_vals[(b * Hh + d) * Ss + s] = tanhf(va);
    }
}

// ================= persistent-kernel phases =================

// LSTM layer: blocks 0..127, 4 gate-rows per block, split-K=4 (16 warps).
// Weights + activations via L1 (smem is minimal so L1 is ~217KB).
__device__ __forceinline__ void phase_lstm(
    float* red, const longlong2* xT, int layer,
    const longlong2* __restrict__ Wih, const longlong2* __restrict__ Whh,
    const float* __restrict__ bih, const float* __restrict__ bhh) {
    int blk = blockIdx.x;
    if (blk >= 128) return;
    int tid = threadIdx.x;
    int wid = tid >> 5, b = tid & 31;
    int rl = wid >> 2, split = wid & 3;
    int jj = blk * 4 + rl;
    const longlong2* hT = (const longlong2*)g_hA[layer];

    ull acc[4] = {0ull, 0ull, 0ull, 0ull};
    int k4b = split * 32;
#pragma unroll 2
    for (int i = 0; i < 32; i++) {
        int k4 = k4b + i;
        longlong2 xv = xT[k4 * Bz + b];
        longlong2 hv = hT[k4 * Bz + b];
#pragma unroll
        for (int g = 0; g < 4; g++) {
            longlong2 wi = Wih[(g * Hh + jj) * (Hh / 4) + k4];
            longlong2 wh = Whh[(g * Hh + jj) * (Hh / 4) + k4];
            fma2(acc[g], (ull)wi.x, (ull)xv.x);
            fma2(acc[g], (ull)wi.y, (ull)xv.y);
            fma2(acc[g], (ull)wh.x, (ull)hv.x);
            fma2(acc[g], (ull)wh.y, (ull)hv.y);
        }
    }
#pragma unroll
    for (int g = 0; g < 4; g++)
        red[((rl * 4 + split) * 4 + g) * 32 + b] = unpk_sum(acc[g]);
    __syncthreads();
    if (tid < 128) {
        int r2 = tid >> 5, bb = tid & 31;
        int j2 = blk * 4 + r2;
        float gate[4];
#pragma unroll
        for (int g = 0; g < 4; g++) {
            float s = 0.f;
#pragma unroll
            for (int sp = 0; sp < 4; sp++) s += red[((r2 * 4 + sp) * 4 + g) * 32 + bb];
            gate[g] = s + bih[g * Hh + j2] + bhh[g * Hh + j2];
        }
        float iv = sigf(gate[0]), fv = sigf(gate[1]);
        float gv = tanhf(gate[2]), ov = sigf(gate[3]);
        int ci = j2 * Bz + bb;
        float c2 = fv * g_cT[layer][ci] + iv * gv;
        g_cT[layer][ci] = c2;
        g_hB[layer][K4B(j2, bb)] = ov * tanhf(c2);
    }
}

// projection over nblk blocks starting at blk0. tasks 0..1249 of 8 vocab rows each.
// Weights streamed with .cs (no L1 pollution); res written with .cs.
__device__ __forceinline__ void phase_proj(
    ull* samax, const longlong2* __restrict__ W, const float* __restrict__ pb,
    float* __restrict__ res, int t, int src_emb, int do_amax, int blk0, int nblk) {
    int tid = threadIdx.x;
    if (do_amax) {
        if (tid < Bz) samax[tid] = 0ull;
        __syncthreads();
    }
    int task = (tid >> 5) * nblk + (blockIdx.x - blk0);
    int b = tid & 31;
    const longlong2* xT = src_emb ? (const longlong2*)g_embT : (const longlong2*)g_hB[1];
    if (task < 1250) {
        int v0 = task * 8;
        ull acc[8] = {0ull, 0ull, 0ull, 0ull, 0ull, 0ull, 0ull, 0ull};
#pragma unroll 2
        for (int k4 = 0; k4 < Hh / 4; k4++) {
            longlong2 xv = xT[k4 * Bz + b];
#pragma unroll
            for (int r = 0; r < 8; r++) {
                longlong2 wv = ldg_cs(&W[(v0 + r) * (Hh / 4) + k4]);
                fma2(acc[r], (ull)wv.x, (ull)xv.x);
                fma2(acc[r], (ull)wv.y, (ull)xv.y);
            }
        }
        ull best = 0ull;
#pragma unroll
        for (int r = 0; r < 8; r++) {
            int v = v0 + r;
            float lg = unpk_sum(acc[r]) + pb[v];
            stg_cs(&res[b * (Vv * Tt) + v * Tt + t], lg);
            ull pk = ((ull)fkey(lg) << 32) | (unsigned)(~(unsigned)v);
            if (pk > best) best = pk;
        }
        if (do_amax) atomicMax(&samax[b], best);
    }
    if (do_amax) { __syncthreads(); if (tid < Bz) atomicMax(&g_amax[tid], samax[tid]); }
}

// q = tanh(h @ Wq^T + bq). Group B (blocks 0..63): 1024 warps = (d, layer) tasks.
__device__ __forceinline__ void phase_q(const longlong2* __restrict__ Wq,
                                        const float* __restrict__ bq) {
    int tid = threadIdx.x;
    int task = (tid >> 5) * 64 + blockIdx.x;   // 0..1023
    int b = tid & 31;
    int d = task >> 1, l = task & 1;
    const longlong2* h = (const longlong2*)g_hB[l];
    ull a = 0ull;
#pragma unroll 4
    for (int k4 = 0; k4 < Hh / 4; k4++) {
        longlong2 wv = ldg_cs(&Wq[d * (Hh / 4) + k4]);
        longlong2 x = h[k4 * Bz + b];
        fma2(a, (ull)wv.x, (ull)x.x);
        fma2(a, (ull)wv.y, (ull)x.y);
    }
    g_q[l][d][b] = tanhf(unpk_sum(a) + bq[d]);
}

// attention: group B blocks 0..63 = (l, b) tasks.
__device__ __forceinline__ void phase_att(float* sq, float* sw) {
    int l = blockIdx.x >> 5, b = blockIdx.x & 31;
    int tid = threadIdx.x;
    for (int d = tid; d < Hh; d += 512) sq[d] = g_q[l][d][b];
    __syncthreads();
    int w = tid >> 5, lane = tid & 31;
    for (int s = w; s < Ss; s += 16) {
        const float* kr = g_keysT + (b * Ss + s) * Hh;
        float acc = 0.f;
        for (int d = lane; d < Hh; d += 32) acc = fmaf(sq[d], kr[d], acc);
#pragma unroll
        for (int o = 16; o > 0; o >>= 1) acc += __shfl_down_sync(0xffffffffu, acc, o);
        if (lane == 0) sw[s] = acc * (1.0f / 7.0f);
    }
    __syncthreads();
    if (w == 0) {
        float v0 = (lane < Ss) ? sw[lane] : -3.4e38f;
        float v1 = (lane + 32 < Ss) ? sw[lane + 32] : -3.4e38f;
        float m = fmaxf(v0, v1);
#pragma unroll
        for (int o = 16; o > 0; o >>= 1) m = fmaxf(m, __shfl_xor_sync(0xffffffffu, m, o));
        float e0 = (lane < Ss) ? expf(v0 - m) : 0.f;
        float e1 = (lane + 32 < Ss) ? expf(v1 - m) : 0.f;
        float sum = e0 + e1;
#pragma unroll
        for (int o = 16; o > 0; o >>= 1) sum += __shfl_xor_sync(0xffffffffu, sum, o);
        float inv = 1.0f / sum;
        if (lane < Ss) sw[lane] = e0 * inv;
        if (lane + 32 < Ss) sw[lane + 32] = e1 * inv;
    }
    __syncthreads();
    for (int d = tid; d < Hh; d += 512) {
        const float* vr = g_vals + (b * Hh + d) * Ss;
        float a = 0.f;
#pragma unroll
        for (int s = 0; s < Ss; s++) a = fmaf(sw[s], vr[s], a);
        g_attnT[l][K4B(d, b)] = a;
    }
}

// greedy-token embedding gather: group A blocks 64..95 (one per batch element).
__device__ __forceinline__ void phase_gather(const float* __restrict__ embed) {
    int b = blockIdx.x - 64;
    unsigned vtok = ~(unsigned)(g_amax[b]);
    int k = threadIdx.x;
    g_embT[K4B(k, b)] = embed[(size_t)vtok * Hh + k];
    __syncthreads();
    if (threadIdx.x == 0) g_amax[b] = 0ull;
}

// gated hidden update: group B blocks 0..63, 8 output dims per block, split-K=2,
// each warp does both layers for its (dim, K-half).
__device__ __forceinline__ void phase_hatt(float* red, const longlong2* __restrict__ Wh,
                                           const float* __restrict__ hb) {
    int blk = blockIdx.x;
    int tid = threadIdx.x;
    int wid = tid >> 5, b = tid & 31;
    int dl = wid & 7, split = wid >> 3;
    int d = blk * 8 + dl;
    const longlong2* at0 = (const longlong2*)g_attnT[0];
    const longlong2* at1 = (const longlong2*)g_attnT[1];
    const longlong2* h0 = (const longlong2*)g_hB[0];
    const longlong2* h1 = (const longlong2*)g_hB[1];
    ull a0 = 0ull, a1 = 0ull;
    int k4b = split * 64;
#pragma unroll 2
    for (int i = 0; i < 64; i++) {
        int k4 = k4b + i;
        longlong2 wA = ldg_cs(&Wh[d * 256 + k4]);          // attn half
        longlong2 wH = ldg_cs(&Wh[d * 256 + 128 + k4]);    // h half
        longlong2 av0 = at0[k4 * Bz + b], av1 = at1[k4 * Bz + b];
        longlong2 hv0 = h0[k4 * Bz + b], hv1 = h1[k4 * Bz + b];
        fma2(a0, (ull)wA.x, (ull)av0.x);
        fma2(a0, (ull)wA.y, (ull)av0.y);
        fma2(a0, (ull)wH.x, (ull)hv0.x);
        fma2(a0, (ull)wH.y, (ull)hv0.y);
        fma2(a1, (ull)wA.x, (ull)av1.x);
        fma2(a1, (ull)wA.y, (ull)av1.y);
        fma2(a1, (ull)wH.x, (ull)hv1.x);
        fma2(a1, (ull)wH.y, (ull)hv1.y);
    }
    red[((dl * 2 + split) * 2 + 0) * 32 + b] = unpk_sum(a0);
    red[((dl * 2 + split) * 2 + 1) * 32 + b] = unpk_sum(a1);
    __syncthreads();
    {
        int dl2 = tid >> 6, l2 = (tid >> 5) & 1, bb = tid & 31;
        int d2 = blk * 8 + dl2;
        float s = red[((dl2 * 2 + 0) * 2 + l2) * 32 + bb]
                + red[((dl2 * 2 + 1) * 2 + l2) * 32 + bb];
        g_hA[l2][K4B(d2, bb)] = tanhf(s + hb[d2]);
    }
}

// ---------------- the persistent time-loop kernel ----------------
__global__ __launch_bounds__(512, 1) void k_loop(
    const float* __restrict__ pooled, const float* __restrict__ embed,
    const int* __restrict__ sosp,
    const longlong2* __restrict__ Wih, const longlong2* __restrict__ Whh,
    const float* __restrict__ bih, const float* __restrict__ bhh,
    const longlong2* __restrict__ projW, const float* __restrict__ projb,
    const longlong2* __restrict__ Wq, const float* __restrict__ bq,
    const longlong2* __restrict__ hattW, const float* __restrict__ hattb,
    float* __restrict__ res) {
    __shared__ float red[2048];        // 8KB (lstm + hatt reductions)
    __shared__ float sq[Hh];
    __shared__ float sw[64];
    __shared__ ull samax[Bz];
    __shared__ int s_bF, s_bA, s_bB;

    if (threadIdx.x == 0) {
        s_bF = *(volatile int*)&g_gen;
        s_bA = *(volatile int*)&gA_gen;
        s_bB = *(volatile int*)&gB_gen;
    }
    __syncthreads();
    int genF = s_bF, genA = s_bA, genB = s_bB;

    // ---- init ----
    {
        int i = blockIdx.x * 512 + threadIdx.x;
        int sos = sosp[0];
        if (i < Ll * Hh * Bz) {
            int l = i / (Hh * Bz);
            int r = i % (Hh * Bz);
            int k = r >> 5, b = r & 31;
            float pv = pooled[b * Hh + k];
            g_hA[l][K4B(k, b)] = pv;
            g_cT[l][k * Bz + b] = pv;
        }
        if (i < Hh * Bz) {
            int k = i >> 5, b = i & 31;
            g_embT[K4B(k, b)] = embed[sos * Hh + k];
        }
        if (i < Bz) g_amax[i] = 0ull;
    }
    bar_n(&g_count, &g_gen, GRID, ++genF);

    // t = 0 column from the <SOS> embedding (all blocks, no argmax)
    phase_proj(samax, projW, projb, res, 0, 1, 0, 0, GRID);
    bar_n(&g_count, &g_gen, GRID, ++genF);

    const longlong2* Wih1 = Wih + 4 * Hh * (Hh / 4);
    const longlong2* Whh1 = Whh + 4 * Hh * (Hh / 4);

    for (int t = 1; t < Tt; t++) {
        phase_lstm(red, (const longlong2*)g_embT, 0, Wih, Whh, bih, bhh);
        bar_n(&g_count, &g_gen, GRID, ++genF);
        phase_lstm(red, (const longlong2*)g_hB[0], 1, Wih1, Whh1, bih + 4 * Hh, bhh + 4 * Hh);
        bar_n(&g_count, &g_gen, GRID, ++genF);
        if (blockIdx.x >= 64) {
            // group A: projection + argmax -> next-token embedding gather
            phase_proj(samax, projW, projb, res, t, 0, 1, 64, 84);
            bar_n(&gA_count, &gA_gen, 84, ++genA);
            if (blockIdx.x < 96) phase_gather(embed);
        } else {
            // group B: q -> attention -> gated hidden update
            phase_q(Wq, bq);
            bar_n(&gB_count, &gB_gen, 64, ++genB);
            phase_att(sq, sw);
            bar_n(&gB_count, &gB_gen, 64, ++genB);
            phase_hatt(red, hattW, hattb);
        }
        bar_n(&g_count, &g_gen, GRID, ++genF);
    }
}

// ---------------- launch ----------------
extern "C" void kernel_launch(void* const* d_in, const int* in_sizes, int n_in,
                              void* d_out, int out_size) {
    (void)in_sizes; (void)n_in; (void)out_size;
    const float* img    = (const float*)d_in[0];
    const float* pooled = (const float*)d_in[1];
    const float* embed  = (const float*)d_in[2];
    const float* Wq     = (const float*)d_in[3];
    const float* bq     = (const float*)d_in[4];
    const float* Wk     = (const float*)d_in[5];
    const float* bk     = (const float*)d_in[6];
    const float* Wv     = (const float*)d_in[7];
    const float* bv     = (const float*)d_in[8];
    const float* Wih    = (const float*)d_in[9];
    const float* Whh    = (const float*)d_in[10];
    const float* bih    = (const float*)d_in[11];
    const float* bhh    = (const float*)d_in[12];
    const float* projW  = (const float*)d_in[13];
    const float* projb  = (const float*)d_in[14];
    const float* hattW  = (const float*)d_in[15];
    const float* hattb  = (const float*)d_in[16];
    const int*   sosp   = (const int*)d_in[17];
    float* res = (float*)d_out;

    k_kv<<<Bz * Hh, 64>>>(img, Wk, bk, Wv, bv);
    k_loop<<<GRID, 512>>>(pooled, embed, sosp,
                          (const longlong2*)Wih, (const longlong2*)Whh, bih, bhh,
                          (const longlong2*)projW, projb,
                          (const longlong2*)Wq, bq,
                          (const longlong2*)hattW, hattb,
                          res);
}

// round 12
// speedup vs baseline: 1.7109x; 1.1295x over previous
#include <cuda_runtime.h>
#include <cstdint>

#define Bz 32
#define Hh 512
#define Ll 2
#define Tt 20
#define Vv 10000
#define Ss 49
#define GRID 148

typedef unsigned long long ull;

// ---------------- device state (no allocations allowed) ----------------
__device__ __align__(16) float g_embT[Hh * Bz];          // k4b4 layout
__device__ __align__(16) float g_hA[Ll][Hh * Bz];        // gated h (LSTM input), k4b4
__device__ __align__(16) float g_hB[Ll][Hh * Bz];        // post-LSTM h, k4b4
__device__ __align__(16) float g_cT[Ll][Hh * Bz];        // plain [k*32+b]
__device__ __align__(16) float g_attnT[Ll][Hh * Bz];     // k4b4
__device__ float g_q[Ll][Hh][Bz];
__device__ float g_keysT[Bz * Ss * Hh];                  // [b][s][d]
__device__ float g_vals[Bz * Ss * Hh];                   // [b][s][d]  (coalesced attn reads)
__device__ ull   g_amax[Bz];
__device__ int   g_count,  g_gen;    // full-grid barrier
__device__ int   gA_count, gA_gen;   // group A (blocks 48..147, n=100)
__device__ int   gB_count, gB_gen;   // group B (blocks 0..47,  n=48)

// ---------------- helpers ----------------
__device__ __forceinline__ void fma2(ull& d, ull a, ull b) {
    asm("fma.rn.f32x2 %0, %1, %2, %0;" : "+l"(d) : "l"(a), "l"(b));
}
__device__ __forceinline__ float unpk_sum(ull v) {
    float lo, hi;
    asm("mov.b64 {%0,%1}, %2;" : "=f"(lo), "=f"(hi) : "l"(v));
    return lo + hi;
}
__device__ __forceinline__ longlong2 ldg_cs(const longlong2* p) {
    longlong2 v;
    asm("ld.global.cs.v2.u64 {%0,%1}, [%2];" : "=l"(v.x), "=l"(v.y) : "l"(p));
    return v;
}
__device__ __forceinline__ void stg_cs(float* p, float v) {
    asm("st.global.cs.f32 [%0], %1;" :: "l"(p), "f"(v) : "memory");
}
__device__ __forceinline__ int K4B(int k, int b) { return ((k >> 2) * Bz + b) * 4 + (k & 3); }
__device__ __forceinline__ float sigf(float x) { return 1.0f / (1.0f + expf(-x)); }
__device__ __forceinline__ unsigned fkey(float f) {
    unsigned u = __float_as_uint(f);
    return (u & 0x80000000u) ? ~u : (u | 0x80000000u);
}

// barrier over n blocks (monotonic generation; co-residency guaranteed at grid=148)
__device__ __forceinline__ void bar_n(int* cnt, int* genp, int n, int gen) {
    __syncthreads();
    if (threadIdx.x == 0) {
        __threadfence();
        if (atomicAdd(cnt, 1) == n - 1) {
            *cnt = 0;
            __threadfence();
            asm volatile("st.release.gpu.b32 [%0], %1;" :: "l"(genp), "r"(gen) : "memory");
        } else {
            int v;
            do {
                asm volatile("ld.acquire.gpu.b32 %0, [%1];" : "=r"(v) : "l"(genp) : "memory");
            } while (v < gen);
        }
    }
    __syncthreads();
}

// ---------------- keys/values precompute (separate kernel, once per launch) ----------------
__global__ void k_kv(const float* __restrict__ img, const float* __restrict__ Wk,
                     const float* __restrict__ bk, const float* __restrict__ Wv,
                     const float* __restrict__ bv) {
    int bd = blockIdx.x;               // b*512 + d
    int b = bd >> 9, d = bd & 511;
    __shared__ float ch[Ss];
    int tid = threadIdx.x;
    if (tid < Ss) ch[tid] = img[(b * Hh + d) * Ss + tid];
    __syncthreads();
    if (tid < Ss) {
        int s = tid;
        float ka = bk[s], va = bv[s];
        const float* wkr = Wk + s * Ss;
        const float* wvr = Wv + s * Ss;
#pragma unroll
        for (int s2 = 0; s2 < Ss; s2++) {
            float c = ch[s2];
            ka = fmaf(c, wkr[s2], ka);
            va = fmaf(c, wvr[s2], va);
        }
        g_keysT[(b * Ss + s) * Hh + d] = tanhf(ka);
        g_vals[(b * Ss + s) * Hh + d] = tanhf(va);
    }
}

// ================= persistent-kernel phases =================

// LSTM layer: blocks 0..127, 4 gate-rows per block, split-K=4 (16 warps).
__device__ __forceinline__ void phase_lstm(
    float* red, const longlong2* xT, int layer,
    const longlong2* __restrict__ Wih, const longlong2* __restrict__ Whh,
    const float* __restrict__ bih, const float* __restrict__ bhh) {
    int blk = blockIdx.x;
    if (blk >= 128) return;
    int tid = threadIdx.x;
    int wid = tid >> 5, b = tid & 31;
    int rl = wid >> 2, split = wid & 3;
    int jj = blk * 4 + rl;
    const longlong2* hT = (const longlong2*)g_hA[layer];

    ull acc[4] = {0ull, 0ull, 0ull, 0ull};
    int k4b = split * 32;
#pragma unroll 2
    for (int i = 0; i < 32; i++) {
        int k4 = k4b + i;
        longlong2 xv = xT[k4 * Bz + b];
        longlong2 hv = hT[k4 * Bz + b];
#pragma unroll
        for (int g = 0; g < 4; g++) {
            longlong2 wi = Wih[(g * Hh + jj) * (Hh / 4) + k4];
            longlong2 wh = Whh[(g * Hh + jj) * (Hh / 4) + k4];
            fma2(acc[g], (ull)wi.x, (ull)xv.x);
            fma2(acc[g], (ull)wi.y, (ull)xv.y);
            fma2(acc[g], (ull)wh.x, (ull)hv.x);
            fma2(acc[g], (ull)wh.y, (ull)hv.y);
        }
    }
#pragma unroll
    for (int g = 0; g < 4; g++)
        red[((rl * 4 + split) * 4 + g) * 32 + b] = unpk_sum(acc[g]);
    __syncthreads();
    if (tid < 128) {
        int r2 = tid >> 5, bb = tid & 31;
        int j2 = blk * 4 + r2;
        float gate[4];
#pragma unroll
        for (int g = 0; g < 4; g++) {
            float s = 0.f;
#pragma unroll
            for (int sp = 0; sp < 4; sp++) s += red[((r2 * 4 + sp) * 4 + g) * 32 + bb];
            gate[g] = s + bih[g * Hh + j2] + bhh[g * Hh + j2];
        }
        float iv = sigf(gate[0]), fv = sigf(gate[1]);
        float gv = tanhf(gate[2]), ov = sigf(gate[3]);
        int ci = j2 * Bz + bb;
        float c2 = fv * g_cT[layer][ci] + iv * gv;
        g_cT[layer][ci] = c2;
        g_hB[layer][K4B(j2, bb)] = ov * tanhf(c2);
    }
}

// projection over nblk blocks starting at blk0. tasks 0..1249 of 8 vocab rows each.
__device__ __forceinline__ void phase_proj(
    ull* samax, const longlong2* __restrict__ W, const float* __restrict__ pb,
    float* __restrict__ res, int t, int src_emb, int do_amax, int blk0, int nblk) {
    int tid = threadIdx.x;
    if (do_amax) {
        if (tid < Bz) samax[tid] = 0ull;
        __syncthreads();
    }
    int task = (tid >> 5) * nblk + (blockIdx.x - blk0);
    int b = tid & 31;
    const longlong2* xT = src_emb ? (const longlong2*)g_embT : (const longlong2*)g_hB[1];
    if (task < 1250) {
        int v0 = task * 8;
        ull acc[8] = {0ull, 0ull, 0ull, 0ull, 0ull, 0ull, 0ull, 0ull};
#pragma unroll 2
        for (int k4 = 0; k4 < Hh / 4; k4++) {
            longlong2 xv = xT[k4 * Bz + b];
#pragma unroll
            for (int r = 0; r < 8; r++) {
                longlong2 wv = ldg_cs(&W[(v0 + r) * (Hh / 4) + k4]);
                fma2(acc[r], (ull)wv.x, (ull)xv.x);
                fma2(acc[r], (ull)wv.y, (ull)xv.y);
            }
        }
        ull best = 0ull;
#pragma unroll
        for (int r = 0; r < 8; r++) {
            int v = v0 + r;
            float lg = unpk_sum(acc[r]) + pb[v];
            stg_cs(&res[b * (Vv * Tt) + v * Tt + t], lg);
            ull pk = ((ull)fkey(lg) << 32) | (unsigned)(~(unsigned)v);
            if (pk > best) best = pk;
        }
        if (do_amax) atomicMax(&samax[b], best);
    }
    if (do_amax) { __syncthreads(); if (tid < Bz) atomicMax(&g_amax[tid], samax[tid]); }
}

// q = tanh(h @ Wq^T + bq). Blocks 0..31: warp = 4 dims x both layers x split-K=4.
__device__ __forceinline__ void phase_q(float* red, const longlong2* __restrict__ Wq,
                                        const float* __restrict__ bq) {
    int tid = threadIdx.x;
    int blk = blockIdx.x;
    int wid = tid >> 5, b = tid & 31;
    int task = blk * 16 + wid;
    if (task < 512) {
        int dgl = wid >> 2, split = wid & 3;
        int d0 = (blk * 4 + dgl) * 4;
        const longlong2* h0 = (const longlong2*)g_hB[0];
        const longlong2* h1 = (const longlong2*)g_hB[1];
        ull a[4][2] = {};
        int k4b = split * 32;
#pragma unroll 2
        for (int i = 0; i < 32; i++) {
            int k4 = k4b + i;
            longlong2 x0 = h0[k4 * Bz + b];
            longlong2 x1 = h1[k4 * Bz + b];
#pragma unroll
            for (int r = 0; r < 4; r++) {
                longlong2 wv = ldg_cs(&Wq[(d0 + r) * (Hh / 4) + k4]);
                fma2(a[r][0], (ull)wv.x, (ull)x0.x);
                fma2(a[r][0], (ull)wv.y, (ull)x0.y);
                fma2(a[r][1], (ull)wv.x, (ull)x1.x);
                fma2(a[r][1], (ull)wv.y, (ull)x1.y);
            }
        }
#pragma unroll
        for (int r = 0; r < 4; r++) {
            red[((wid * 4 + r) * 2 + 0) * 32 + b] = unpk_sum(a[r][0]);
            red[((wid * 4 + r) * 2 + 1) * 32 + b] = unpk_sum(a[r][1]);
        }
    }
    __syncthreads();
    if (blk < 32) {
        for (int o = tid; o < 1024; o += 512) {
            int dgl = o >> 8, r = (o >> 6) & 3, l = (o >> 5) & 1, bb = o & 31;
            float s = 0.f;
#pragma unroll
            for (int sp = 0; sp < 4; sp++)
                s += red[(((dgl * 4 + sp) * 4 + r) * 2 + l) * 32 + bb];
            int d = (blk * 4 + dgl) * 4 + r;
            g_q[l][d][bb] = tanhf(s + bq[d]);
        }
    }
}

// attention: tasks (l,b) over blocks 0..47 (two passes for blk<16). Coalesced vals.
__device__ __forceinline__ void phase_att(float* sq, float* sw) {
    int tid = threadIdx.x;
    for (int task = blockIdx.x; task < 64; task += 48) {
        int l = task >> 5, b = task & 31;
        __syncthreads();
        for (int d = tid; d < Hh; d += 512) sq[d] = g_q[l][d][b];
        __syncthreads();
        int w = tid >> 5, lane = tid & 31;
        for (int s = w; s < Ss; s += 16) {
            const float* kr = g_keysT + (b * Ss + s) * Hh;
            float acc = 0.f;
            for (int d = lane; d < Hh; d += 32) acc = fmaf(sq[d], kr[d], acc);
#pragma unroll
            for (int o = 16; o > 0; o >>= 1) acc += __shfl_down_sync(0xffffffffu, acc, o);
            if (lane == 0) sw[s] = acc * (1.0f / 7.0f);
        }
        __syncthreads();
        if (w == 0) {
            float v0 = (lane < Ss) ? sw[lane] : -3.4e38f;
            float v1 = (lane + 32 < Ss) ? sw[lane + 32] : -3.4e38f;
            float m = fmaxf(v0, v1);
#pragma unroll
            for (int o = 16; o > 0; o >>= 1) m = fmaxf(m, __shfl_xor_sync(0xffffffffu, m, o));
            float e0 = (lane < Ss) ? expf(v0 - m) : 0.f;
            float e1 = (lane + 32 < Ss) ? expf(v1 - m) : 0.f;
            float sum = e0 + e1;
#pragma unroll
            for (int o = 16; o > 0; o >>= 1) sum += __shfl_xor_sync(0xffffffffu, sum, o);
            float inv = 1.0f / sum;
            if (lane < Ss) sw[lane] = e0 * inv;
            if (lane + 32 < Ss) sw[lane + 32] = e1 * inv;
        }
        __syncthreads();
        for (int d = tid; d < Hh; d += 512) {
            float a = 0.f;
#pragma unroll
            for (int s = 0; s < Ss; s++)
                a = fmaf(sw[s], g_vals[(b * Ss + s) * Hh + d], a);
            g_attnT[l][K4B(d, b)] = a;
        }
    }
}

// greedy-token embedding gather: blocks 48..79 (one per batch element).
__device__ __forceinline__ void phase_gather(const float* __restrict__ embed) {
    int b = blockIdx.x - 48;
    unsigned vtok = ~(unsigned)(g_amax[b]);
    int k = threadIdx.x;
    g_embT[K4B(k, b)] = embed[(size_t)vtok * Hh + k];
    __syncthreads();
    if (threadIdx.x == 0) g_amax[b] = 0ull;
}

// gated hidden update. Blocks 0..31: warp = 8 dims x both layers x split-K=8.
__device__ __forceinline__ void phase_hatt(float* red, const longlong2* __restrict__ Wh,
                                           const float* __restrict__ hb) {
    int tid = threadIdx.x;
    int blk = blockIdx.x;
    int wid = tid >> 5, b = tid & 31;
    int task = blk * 16 + wid;
    if (task < 512) {
        int dgl = wid >> 3, split = wid & 7;
        int d0 = (blk * 2 + dgl) * 8;
        const longlong2* at0 = (const longlong2*)g_attnT[0];
        const longlong2* at1 = (const longlong2*)g_attnT[1];
        const longlong2* h0 = (const longlong2*)g_hB[0];
        const longlong2* h1 = (const longlong2*)g_hB[1];
        ull a[8][2] = {};
        int k4b = split * 16;
#pragma unroll 2
        for (int i = 0; i < 16; i++) {
            int k4 = k4b + i;
            longlong2 av0 = at0[k4 * Bz + b], av1 = at1[k4 * Bz + b];
            longlong2 hv0 = h0[k4 * Bz + b], hv1 = h1[k4 * Bz + b];
#pragma unroll
            for (int r = 0; r < 8; r++) {
                longlong2 wA = ldg_cs(&Wh[(d0 + r) * 256 + k4]);
                longlong2 wH = ldg_cs(&Wh[(d0 + r) * 256 + 128 + k4]);
                fma2(a[r][0], (ull)wA.x, (ull)av0.x);
                fma2(a[r][0], (ull)wA.y, (ull)av0.y);
                fma2(a[r][0], (ull)wH.x, (ull)hv0.x);
                fma2(a[r][0], (ull)wH.y, (ull)hv0.y);
                fma2(a[r][1], (ull)wA.x, (ull)av1.x);
                fma2(a[r][1], (ull)wA.y, (ull)av1.y);
                fma2(a[r][1], (ull)wH.x, (ull)hv1.x);
                fma2(a[r][1], (ull)wH.y, (ull)hv1.y);
            }
        }
#pragma unroll
        for (int r = 0; r < 8; r++) {
            red[(wid * 16 + r * 2 + 0) * 32 + b] = unpk_sum(a[r][0]);
            red[(wid * 16 + r * 2 + 1) * 32 + b] = unpk_sum(a[r][1]);
        }
    }
    __syncthreads();
    if (blk < 32) {
        for (int o = tid; o < 1024; o += 512) {
            int dgl = o >> 9, r = (o >> 6) & 7, l = (o >> 5) & 1, bb = o & 31;
            float s = 0.f;
#pragma unroll
            for (int sp = 0; sp < 8; sp++)
                s += red[((dgl * 8 + sp) * 16 + r * 2 + l) * 32 + bb];
            int d = (blk * 2 + dgl) * 8 + r;
            g_hA[l][K4B(d, bb)] = tanhf(s + hb[d]);
        }
    }
}

// ---------------- the persistent time-loop kernel ----------------
__global__ __launch_bounds__(512, 1) void k_loop(
    const float* __restrict__ pooled, const float* __restrict__ embed,
    const int* __restrict__ sosp,
    const longlong2* __restrict__ Wih, const longlong2* __restrict__ Whh,
    const float* __restrict__ bih, const float* __restrict__ bhh,
    const longlong2* __restrict__ projW, const float* __restrict__ projb,
    const longlong2* __restrict__ Wq, const float* __restrict__ bq,
    const longlong2* __restrict__ hattW, const float* __restrict__ hattb,
    float* __restrict__ res) {
    __shared__ float red[8192];        // 32KB (lstm / q / hatt reductions)
    __shared__ float sq[Hh];
    __shared__ float sw[64];
    __shared__ ull samax[Bz];
    __shared__ int s_bF, s_bA, s_bB;

    if (threadIdx.x == 0) {
        s_bF = *(volatile int*)&g_gen;
        s_bA = *(volatile int*)&gA_gen;
        s_bB = *(volatile int*)&gB_gen;
    }
    __syncthreads();
    int genF = s_bF, genA = s_bA, genB = s_bB;

    // ---- init ----
    {
        int i = blockIdx.x * 512 + threadIdx.x;
        int sos = sosp[0];
        if (i < Ll * Hh * Bz) {
            int l = i / (Hh * Bz);
            int r = i % (Hh * Bz);
            int k = r >> 5, b = r & 31;
            float pv = pooled[b * Hh + k];
            g_hA[l][K4B(k, b)] = pv;
            g_cT[l][k * Bz + b] = pv;
        }
        if (i < Hh * Bz) {
            int k = i >> 5, b = i & 31;
            g_embT[K4B(k, b)] = embed[sos * Hh + k];
        }
        if (i < Bz) g_amax[i] = 0ull;
    }
    bar_n(&g_count, &g_gen, GRID, ++genF);

    // t = 0 column from the <SOS> embedding (all blocks, no argmax)
    phase_proj(samax, projW, projb, res, 0, 1, 0, 0, GRID);
    bar_n(&g_count, &g_gen, GRID, ++genF);

    const longlong2* Wih1 = Wih + 4 * Hh * (Hh / 4);
    const longlong2* Whh1 = Whh + 4 * Hh * (Hh / 4);

    for (int t = 1; t < Tt; t++) {
        phase_lstm(red, (const longlong2*)g_embT, 0, Wih, Whh, bih, bhh);
        bar_n(&g_count, &g_gen, GRID, ++genF);
        phase_lstm(red, (const longlong2*)g_hB[0], 1, Wih1, Whh1, bih + 4 * Hh, bhh + 4 * Hh);
        bar_n(&g_count, &g_gen, GRID, ++genF);
        if (blockIdx.x >= 48) {
            // group A: projection + argmax -> next-token embedding gather
            phase_proj(samax, projW, projb, res, t, 0, 1, 48, 100);
            bar_n(&gA_count, &gA_gen, 100, ++genA);
            if (blockIdx.x < 80) phase_gather(embed);
        } else {
            // group B: q -> attention -> gated hidden update
            phase_q(red, Wq, bq);
            bar_n(&gB_count, &gB_gen, 48, ++genB);
            phase_att(sq, sw);
            bar_n(&gB_count, &gB_gen, 48, ++genB);
            phase_hatt(red, hattW, hattb);
        }
        bar_n(&g_count, &g_gen, GRID, ++genF);
    }
}

// ---------------- launch ----------------
extern "C" void kernel_launch(void* const* d_in, const int* in_sizes, int n_in,
                              void* d_out, int out_size) {
    (void)in_sizes; (void)n_in; (void)out_size;
    const float* img    = (const float*)d_in[0];
    const float* pooled = (const float*)d_in[1];
    const float* embed  = (const float*)d_in[2];
    const float* Wq     = (const float*)d_in[3];
    const float* bq     = (const float*)d_in[4];
    const float* Wk     = (const float*)d_in[5];
    const float* bk     = (const float*)d_in[6];
    const float* Wv     = (const float*)d_in[7];
    const float* bv     = (const float*)d_in[8];
    const float* Wih    = (const float*)d_in[9];
    const float* Whh    = (const float*)d_in[10];
    const float* bih    = (const float*)d_in[11];
    const float* bhh    = (const float*)d_in[12];
    const float* projW  = (const float*)d_in[13];
    const float* projb  = (const float*)d_in[14];
    const float* hattW  = (const float*)d_in[15];
    const float* hattb  = (const float*)d_in[16];
    const int*   sosp   = (const int*)d_in[17];
    float* res = (float*)d_out;

    k_kv<<<Bz * Hh, 64>>>(img, Wk, bk, Wv, bv);
    k_loop<<<GRID, 512>>>(pooled, embed, sosp,
                          (const longlong2*)Wih, (const longlong2*)Whh, bih, bhh,
                          (const longlong2*)projW, projb,
                          (const longlong2*)Wq, bq,
                          (const longlong2*)hattW, hattb,
                          res);
}